// round 1
// baseline (speedup 1.0000x reference)
#include <cuda_runtime.h>
#include <cstdint>

#define Bn   16
#define Tn   512
#define INn  128
#define Hn   256
#define Dn   8
#define EPSf 1e-5f

// ---------------- scratch (static device arrays; no allocation) ----------------
__device__ float g_xproj[Bn * Tn * Hn];   // 8 MB
__device__ float g_enc  [Bn * Tn * Hn];   // 8 MB
__device__ float g_bd   [Bn * Tn * 2 * Dn]; // 512 KB

// ---------------- helpers ----------------
__device__ __forceinline__ uint32_t smem_u32(const void* p) {
    uint32_t a;
    asm("{ .reg .u64 t; cvta.to.shared.u64 t, %1; cvt.u32.u64 %0, t; }"
        : "=r"(a) : "l"(p));
    return a;
}

__device__ __forceinline__ unsigned long long pack2(float x, float y) {
    unsigned long long r;
    asm("mov.b64 %0, {%1, %2};" : "=l"(r) : "f"(x), "f"(y));
    return r;
}
__device__ __forceinline__ void unpack2(unsigned long long v, float& x, float& y) {
    asm("mov.b64 {%0, %1}, %2;" : "=f"(x), "=f"(y) : "l"(v));
}
// packed fp32x2 FMA (Blackwell FFMA2): 2 fp32 MACs per instruction
__device__ __forceinline__ void ffma2(unsigned long long& d,
                                      unsigned long long a,
                                      unsigned long long b) {
    asm("fma.rn.f32x2 %0, %1, %2, %3;" : "=l"(d) : "l"(a), "l"(b), "l"(d));
}

__device__ __forceinline__ void mbar_wait_cluster(uint32_t addr, int phase) {
    asm volatile(
        "{\n\t"
        ".reg .pred P1;\n\t"
        "LAB_%=:\n\t"
        "mbarrier.try_wait.parity.acquire.cluster.shared::cta.b64 P1, [%0], %1, 0x989680;\n\t"
        "@P1 bra DONE_%=;\n\t"
        "bra LAB_%=;\n\t"
        "DONE_%=:\n\t"
        "}"
        :: "r"(addr), "r"(phase) : "memory");
}

__device__ __forceinline__ void st_remote_f32(uint32_t local_addr, uint32_t peer_rank, float v) {
    asm volatile(
        "{\n\t"
        ".reg .b32 ra;\n\t"
        "mapa.shared::cluster.u32 ra, %0, %1;\n\t"
        "st.shared::cluster.f32 [ra], %2;\n\t"
        "}"
        :: "r"(local_addr), "r"(peer_rank), "f"(v) : "memory");
}

__device__ __forceinline__ void mbar_arrive_remote(uint32_t local_addr, uint32_t peer_rank) {
    asm volatile(
        "{\n\t"
        ".reg .b32 ra;\n\t"
        "mapa.shared::cluster.u32 ra, %0, %1;\n\t"
        "mbarrier.arrive.release.cluster.shared::cluster.b64 _, [ra];\n\t"
        "}"
        :: "r"(local_addr), "r"(peer_rank) : "memory");
}

// ---------------- kernel 1: x_proj = y @ W_ih^T + b_ih ----------------
// grid (T/4, B), block 256. Thread = output channel h; 4 time rows per block.
__global__ void k_xproj(const float* __restrict__ y,
                        const float* __restrict__ W_ih,
                        const float* __restrict__ b_ih) {
    const int h  = threadIdx.x;       // 0..255
    const int b  = blockIdx.y;
    const int t0 = blockIdx.x * 4;

    const float4* Wr = reinterpret_cast<const float4*>(W_ih + h * INn);         // 32 float4
    const float4* Y  = reinterpret_cast<const float4*>(y + ((size_t)b * Tn + t0) * INn);

    float a0 = 0.f, a1 = 0.f, a2 = 0.f, a3 = 0.f;
#pragma unroll 4
    for (int k = 0; k < 32; k++) {
        float4 wv = __ldg(Wr + k);
        float4 y0 = __ldg(Y + k);
        float4 y1 = __ldg(Y + 32 + k);
        float4 y2 = __ldg(Y + 64 + k);
        float4 y3 = __ldg(Y + 96 + k);
        a0 += wv.x * y0.x + wv.y * y0.y + wv.z * y0.z + wv.w * y0.w;
        a1 += wv.x * y1.x + wv.y * y1.y + wv.z * y1.z + wv.w * y1.w;
        a2 += wv.x * y2.x + wv.y * y2.y + wv.z * y2.z + wv.w * y2.w;
        a3 += wv.x * y3.x + wv.y * y3.y + wv.z * y3.z + wv.w * y3.w;
    }
    const float bias = __ldg(b_ih + h);
    size_t base = ((size_t)b * Tn + t0) * Hn + h;
    g_xproj[base]          = a0 + bias;
    g_xproj[base + Hn]     = a1 + bias;
    g_xproj[base + 2 * Hn] = a2 + bias;
    g_xproj[base + 3 * Hn] = a3 + bias;
}

// ---------------- kernel 2: RNN scan ----------------
// 32 CTAs (cluster of 2 per batch), 256 threads.
// CTA rank r owns output rows [r*128, r*128+128). Thread (jloc, kh):
// output j = r*128 + jloc, k-half kh. W_hh slice register-resident (64 f32x2).
// h exchanged cross-CTA per step via DSMEM store + mbarrier (double buffered).
__global__ void __cluster_dims__(2, 1, 1) __launch_bounds__(256, 1)
k_scan(const float* __restrict__ W_hh, const float* __restrict__ b_hh) {
    __shared__ float hbuf[2][Hn];
    __shared__ float partialS[128];
    __shared__ __align__(8) unsigned long long mbar[2];

    const int tid  = threadIdx.x;
    const int jloc = tid & 127;
    const int kh   = tid >> 7;               // 0 or 1
    const unsigned rank  = blockIdx.x & 1;
    const unsigned peer  = rank ^ 1;
    const int batch = blockIdx.x >> 1;
    const int jg    = (int)rank * 128 + jloc;
    const bool k_remote = (kh != (int)rank);  // my k-half is produced by the peer CTA
    const bool writer   = (kh == 0);

    // register-resident weight slice: W_hh[jg, kh*128 .. +128)
    unsigned long long w[64];
    {
        const float2* wrow = reinterpret_cast<const float2*>(W_hh + (size_t)jg * Hn + (kh << 7));
#pragma unroll
        for (int i = 0; i < 64; i++) {
            float2 v = __ldg(wrow + i);
            w[i] = pack2(v.x, v.y);
        }
    }
    float bias = writer ? __ldg(b_hh + jg) : 0.f;
    float xv   = writer ? __ldg(g_xproj + (size_t)batch * Tn * Hn + jg) : 0.f;

    hbuf[0][tid] = 0.f;  // h0 = 0 (tid spans 0..255 = full H)
    if (tid == 0) {
        asm volatile("mbarrier.init.shared.b64 [%0], 128;" :: "r"(smem_u32(&mbar[0])) : "memory");
        asm volatile("mbarrier.init.shared.b64 [%0], 128;" :: "r"(smem_u32(&mbar[1])) : "memory");
    }
    __syncthreads();
    asm volatile("barrier.cluster.arrive.aligned;" ::: "memory");
    asm volatile("barrier.cluster.wait.aligned;" ::: "memory");

    int ph0 = 0, ph1 = 0;

    for (int t = 0; t < Tn; ++t) {
        const int cur = t & 1;
        const int nxt = cur ^ 1;

        // prefetch next step's x early (latency hidden behind FMA loop)
        float xnew = 0.f;
        if (writer && (t + 1) < Tn)
            xnew = __ldg(g_xproj + ((size_t)batch * Tn + t + 1) * Hn + jg);

        // threads whose k-half is peer-produced wait for the peer's arrivals
        if (t > 0 && k_remote) {
            if (cur) { mbar_wait_cluster(smem_u32(&mbar[1]), ph1); ph1 ^= 1; }
            else     { mbar_wait_cluster(smem_u32(&mbar[0]), ph0); ph0 ^= 1; }
        }

        // 128-length dot over my k-half, packed fp32x2 FMAs
        const float4* hp = reinterpret_cast<const float4*>(&hbuf[cur][kh << 7]);
        unsigned long long acc0 = pack2(0.f, 0.f);
        unsigned long long acc1 = pack2(0.f, 0.f);
#pragma unroll
        for (int i = 0; i < 32; i++) {
            float4 hv = hp[i];
            ffma2(acc0, w[2 * i],     pack2(hv.x, hv.y));
            ffma2(acc1, w[2 * i + 1], pack2(hv.z, hv.w));
        }
        float a0, a1, c0, c1;
        unpack2(acc0, a0, a1);
        unpack2(acc1, c0, c1);
        float part = (a0 + c0) + (a1 + c1);

        if (!writer) partialS[jloc] = part;
        __syncthreads();

        if (writer) {
            float s  = part + partialS[jloc] + xv + bias;
            float hn = tanhf(s);
            xv = xnew;
            g_enc[((size_t)batch * Tn + t) * Hn + jg] = hn;
            hbuf[nxt][jg] = hn;                       // local copy
            if (t + 1 < Tn) {
                uint32_t la = smem_u32(&hbuf[nxt][jg]);
                st_remote_f32(la, peer, hn);          // peer's copy via DSMEM
                mbar_arrive_remote(smem_u32(&mbar[nxt]), peer);  // release
            }
        }
        __syncthreads();
    }
}

// ---------------- kernel 3: mean + bd heads ----------------
// block = 192 threads = 8 (b,t)-rows x 24 outputs (8 mean + 16 bd)
__global__ void k_meanbd(const float* __restrict__ W_mean, const float* __restrict__ b_mean,
                         const float* __restrict__ W_bd,   const float* __restrict__ b_bd,
                         float* __restrict__ out_mean) {
    const int local = threadIdx.x;            // 0..191
    const int o  = local % 24;
    const int r  = local / 24;
    const int bt = blockIdx.x * 8 + r;        // 0..8191

    const float4* e4 = reinterpret_cast<const float4*>(g_enc + (size_t)bt * Hn);
    const float4* w4;
    float bias;
    if (o < Dn) { w4 = reinterpret_cast<const float4*>(W_mean + o * Hn);        bias = __ldg(b_mean + o); }
    else        { w4 = reinterpret_cast<const float4*>(W_bd + (o - Dn) * Hn);   bias = __ldg(b_bd + (o - Dn)); }

    float acc = 0.f;
#pragma unroll 8
    for (int k = 0; k < 64; k++) {
        float4 ev = __ldg(e4 + k);
        float4 wv = __ldg(w4 + k);
        acc += ev.x * wv.x + ev.y * wv.y + ev.z * wv.z + ev.w * wv.w;
    }
    acc += bias;
    if (o < Dn) out_mean[(size_t)bt * Dn + o] = acc;
    else        g_bd[(size_t)bt * (2 * Dn) + (o - Dn)] = acc;
}

// ---------------- kernel 4: build tridiagonal prec (B, D, T, T) ----------------
// One float4 per thread; mostly zero stream, special-cased near the diagonal.
__global__ void k_prec(float* __restrict__ prec) {
    const int idx = blockIdx.x * 256 + threadIdx.x;   // 0 .. 8388607
    const int c4  = idx & 127;                        // column group (4 cols)
    const int i   = (idx >> 7) & 511;                 // row within (t,t) block
    const int bd_ = idx >> 16;                        // b*8 + d
    const int d   = bd_ & 7;
    const int b   = bd_ >> 3;

    float4 v = make_float4(0.f, 0.f, 0.f, 0.f);
    const int cb = c4 << 2;

    if (i >= cb - 1 && i <= cb + 4) {
        const size_t row = ((size_t)b * Tn + i) * 16;
        float diag_i = g_bd[row + d];
        float off_i  = g_bd[row + 8 + d];
        float diag_p = 0.f, off_p = 0.f;
        if (i > 0) {
            diag_p = g_bd[row - 16 + d];
            off_p  = g_bd[row - 16 + 8 + d];
        }
        float mainv  = diag_i * diag_i + off_p * off_p + EPSf;
        float supd_l = diag_p * off_p;   // column i-1  (== supd[i-1])
        float supd_r = diag_i * off_i;   // column i+1  (== supd[i]); i=T-1 auto-excluded

        int c;
        c = cb + 0; v.x = (c == i) ? mainv : (c == i - 1) ? supd_l : (c == i + 1) ? supd_r : 0.f;
        c = cb + 1; v.y = (c == i) ? mainv : (c == i - 1) ? supd_l : (c == i + 1) ? supd_r : 0.f;
        c = cb + 2; v.z = (c == i) ? mainv : (c == i - 1) ? supd_l : (c == i + 1) ? supd_r : 0.f;
        c = cb + 3; v.w = (c == i) ? mainv : (c == i - 1) ? supd_l : (c == i + 1) ? supd_r : 0.f;
    }
    reinterpret_cast<float4*>(prec)[idx] = v;
}

// ---------------- launch ----------------
extern "C" void kernel_launch(void* const* d_in, const int* in_sizes, int n_in,
                              void* d_out, int out_size) {
    const float* y      = (const float*)d_in[0];
    const float* W_ih   = (const float*)d_in[1];
    const float* W_hh   = (const float*)d_in[2];
    const float* b_ih   = (const float*)d_in[3];
    const float* b_hh   = (const float*)d_in[4];
    const float* W_mean = (const float*)d_in[5];
    const float* b_mean = (const float*)d_in[6];
    const float* W_bd   = (const float*)d_in[7];
    const float* b_bd   = (const float*)d_in[8];
    float* out = (float*)d_out;

    k_xproj<<<dim3(Tn / 4, Bn), 256>>>(y, W_ih, b_ih);
    k_scan<<<2 * Bn, 256>>>(W_hh, b_hh);
    k_meanbd<<<(Bn * Tn) / 8, 192>>>(W_mean, b_mean, W_bd, b_bd, out);
    k_prec<<<(Bn * Dn * Tn * Tn / 4) / 256, 256>>>(out + Bn * Tn * Dn);
}

// round 2
// speedup vs baseline: 1.3140x; 1.3140x over previous
#include <cuda_runtime.h>
#include <cstdint>

#define Bn   16
#define Tn   512
#define INn  128
#define Hn   256
#define Dn   8
#define EPSf 1e-5f

// ---------------- scratch (static device arrays; no allocation) ----------------
__device__ float g_xproj[Bn * Tn * Hn];   // 8 MB
__device__ float g_enc  [Bn * Tn * Hn];   // 8 MB
__device__ float g_bd   [Bn * Tn * 2 * Dn]; // 512 KB

// ---------------- helpers ----------------
__device__ __forceinline__ uint32_t smem_u32(const void* p) {
    uint32_t a;
    asm("{ .reg .u64 t; cvta.to.shared.u64 t, %1; cvt.u32.u64 %0, t; }"
        : "=r"(a) : "l"(p));
    return a;
}

__device__ __forceinline__ uint32_t cluster_rank() {
    uint32_t r;
    asm("mov.u32 %0, %%cluster_ctarank;" : "=r"(r));
    return r;
}

__device__ __forceinline__ uint32_t mapa_u32(uint32_t local_addr, uint32_t rank) {
    uint32_t r;
    asm("mapa.shared::cluster.u32 %0, %1, %2;" : "=r"(r) : "r"(local_addr), "r"(rank));
    return r;
}

__device__ __forceinline__ unsigned long long pack2(float x, float y) {
    unsigned long long r;
    asm("mov.b64 %0, {%1, %2};" : "=l"(r) : "f"(x), "f"(y));
    return r;
}
__device__ __forceinline__ void unpack2(unsigned long long v, float& x, float& y) {
    asm("mov.b64 {%0, %1}, %2;" : "=f"(x), "=f"(y) : "l"(v));
}
// packed fp32x2 FMA (Blackwell FFMA2): 2 fp32 MACs per instruction
__device__ __forceinline__ void ffma2(unsigned long long& d,
                                      unsigned long long a,
                                      unsigned long long b) {
    asm("fma.rn.f32x2 %0, %1, %2, %3;" : "=l"(d) : "l"(a), "l"(b), "l"(d));
}

__device__ __forceinline__ float tanh_approx(float x) {
    float r;
    asm("tanh.approx.f32 %0, %1;" : "=f"(r) : "f"(x));
    return r;
}

__device__ __forceinline__ void mbar_init(uint32_t addr, uint32_t count) {
    asm volatile("mbarrier.init.shared.b64 [%0], %1;" :: "r"(addr), "r"(count) : "memory");
}

__device__ __forceinline__ void mbar_arrive_expect_tx(uint32_t addr, uint32_t bytes) {
    asm volatile("mbarrier.arrive.expect_tx.shared.b64 _, [%0], %1;"
                 :: "r"(addr), "r"(bytes) : "memory");
}

__device__ __forceinline__ void mbar_wait(uint32_t addr, int phase) {
    asm volatile(
        "{\n\t"
        ".reg .pred P1;\n\t"
        "LAB_%=:\n\t"
        "mbarrier.try_wait.parity.acquire.cta.shared::cta.b64 P1, [%0], %1, 0x989680;\n\t"
        "@P1 bra DONE_%=;\n\t"
        "bra LAB_%=;\n\t"
        "DONE_%=:\n\t"
        "}"
        :: "r"(addr), "r"(phase) : "memory");
}

// one bulk DSMEM copy: local smem -> peer smem, complete_tx on peer's mbarrier
__device__ __forceinline__ void bulk_dsmem(uint32_t dst_cluster, uint32_t src_cta,
                                           uint32_t bytes, uint32_t remote_mbar) {
    asm volatile(
        "cp.async.bulk.shared::cluster.shared::cta.mbarrier::complete_tx::bytes "
        "[%0], [%1], %2, [%3];"
        :: "r"(dst_cluster), "r"(src_cta), "r"(bytes), "r"(remote_mbar) : "memory");
}

__device__ __forceinline__ void fence_async_proxy() {
    asm volatile("fence.proxy.async.shared::cta;" ::: "memory");
}

// ---------------- kernel 1: x_proj = y @ W_ih^T + b_ih ----------------
__global__ void k_xproj(const float* __restrict__ y,
                        const float* __restrict__ W_ih,
                        const float* __restrict__ b_ih) {
    const int h  = threadIdx.x;       // 0..255
    const int b  = blockIdx.y;
    const int t0 = blockIdx.x * 4;

    const float4* Wr = reinterpret_cast<const float4*>(W_ih + h * INn);
    const float4* Y  = reinterpret_cast<const float4*>(y + ((size_t)b * Tn + t0) * INn);

    float a0 = 0.f, a1 = 0.f, a2 = 0.f, a3 = 0.f;
#pragma unroll 4
    for (int k = 0; k < 32; k++) {
        float4 wv = __ldg(Wr + k);
        float4 y0 = __ldg(Y + k);
        float4 y1 = __ldg(Y + 32 + k);
        float4 y2 = __ldg(Y + 64 + k);
        float4 y3 = __ldg(Y + 96 + k);
        a0 += wv.x * y0.x + wv.y * y0.y + wv.z * y0.z + wv.w * y0.w;
        a1 += wv.x * y1.x + wv.y * y1.y + wv.z * y1.z + wv.w * y1.w;
        a2 += wv.x * y2.x + wv.y * y2.y + wv.z * y2.z + wv.w * y2.w;
        a3 += wv.x * y3.x + wv.y * y3.y + wv.z * y3.z + wv.w * y3.w;
    }
    const float bias = __ldg(b_ih + h);
    size_t base = ((size_t)b * Tn + t0) * Hn + h;
    g_xproj[base]          = a0 + bias;
    g_xproj[base + Hn]     = a1 + bias;
    g_xproj[base + 2 * Hn] = a2 + bias;
    g_xproj[base + 3 * Hn] = a3 + bias;
}

// ---------------- kernel 2: RNN scan (partial-sum shipping) ----------------
// 32 CTAs, clusters of 2 (one cluster per batch), 256 threads.
// CTA rank r holds W_hh[:, r*128 : r*128+128] in registers (thread tid = output row).
// Per step: each CTA computes partials for ALL 256 outputs over its local h-half
// (no wait needed), ships the 128 partials belonging to the peer's rows via ONE
// bulk DSMEM copy + complete_tx, then its own-row threads wait for the peer's
// partials, finish s = p_own + p_peer + x + b, h = tanh(s).
__global__ void __cluster_dims__(2, 1, 1) __launch_bounds__(256, 1)
k_scan(const float* __restrict__ W_hh, const float* __restrict__ b_hh) {
    __shared__ __align__(16) float h_cur[128];
    __shared__ __align__(16) float ps_out[2][128];
    __shared__ __align__(16) float ps_in[2][128];
    __shared__ __align__(8) unsigned long long mbar[2];

    const int tid  = threadIdx.x;          // = global output row j
    const int jloc = tid & 127;
    const unsigned rank = cluster_rank();
    const unsigned peer = rank ^ 1;
    const int batch = blockIdx.x >> 1;
    const bool own  = ((tid >> 7) == (int)rank);   // my output row lives in this CTA

    // register-resident weight slice: W_hh[tid, rank*128 .. +128)  (64 f32x2)
    unsigned long long w[64];
    {
        const float2* wr = reinterpret_cast<const float2*>(W_hh + (size_t)tid * Hn + (rank << 7));
#pragma unroll
        for (int i = 0; i < 64; i++) {
            float2 v = __ldg(wr + i);
            w[i] = pack2(v.x, v.y);
        }
    }
    const float bias = own ? __ldg(b_hh + tid) : 0.f;
    const float* xcol = g_xproj + (size_t)batch * Tn * Hn + tid;

    if (tid == 0) { mbar_init(smem_u32(&mbar[0]), 1); mbar_init(smem_u32(&mbar[1]), 1); }
    __syncthreads();
    asm volatile("barrier.cluster.arrive.aligned;" ::: "memory");
    asm volatile("barrier.cluster.wait.aligned;" ::: "memory");

    // precompute remote addresses
    const uint32_t r_ps_in[2] = { mapa_u32(smem_u32(&ps_in[0][0]), peer),
                                  mapa_u32(smem_u32(&ps_in[1][0]), peer) };
    const uint32_t r_mbar[2]  = { mapa_u32(smem_u32(&mbar[0]), peer),
                                  mapa_u32(smem_u32(&mbar[1]), peer) };
    const uint32_t l_ps_out[2] = { smem_u32(&ps_out[0][0]), smem_u32(&ps_out[1][0]) };
    const uint32_t l_mbar[2]   = { smem_u32(&mbar[0]), smem_u32(&mbar[1]) };

    // ---- t = 0: h(0) = tanh(x0 + b), no exchange ----
    if (own) {
        float h0 = tanh_approx(xcol[0] + bias);
        g_enc[((size_t)batch * Tn) * Hn + tid] = h0;
        h_cur[jloc] = h0;
    }
    __syncthreads();

    int ph0 = 0, ph1 = 0;

    for (int t = 1; t < Tn; ++t) {
        const int buf = (t - 1) & 1;

        // issue x prefetch early (LDG latency hidden behind the FMA block)
        float xv = own ? __ldg(xcol + (size_t)t * Hn) : 0.f;

        // receiver posts expected tx for this step's incoming payload
        if (tid == (int)(rank << 7)) mbar_arrive_expect_tx(l_mbar[buf], 512);

        // 128-length dot over LOCAL h-half (available immediately)
        const float4* hp = reinterpret_cast<const float4*>(h_cur);
        unsigned long long acc0 = pack2(0.f, 0.f);
        unsigned long long acc1 = pack2(0.f, 0.f);
#pragma unroll
        for (int i = 0; i < 32; i++) {
            float4 hv = hp[i];
            ffma2(acc0, w[2 * i],     pack2(hv.x, hv.y));
            ffma2(acc1, w[2 * i + 1], pack2(hv.z, hv.w));
        }
        float a0, a1, c0, c1;
        unpack2(acc0, a0, a1);
        unpack2(acc1, c0, c1);
        const float part = (a0 + c0) + (a1 + c1);

        if (!own) ps_out[buf][jloc] = part;   // partial destined for peer's rows
        __syncthreads();

        if (tid == 0) {
            fence_async_proxy();  // make generic STS visible to async proxy
            bulk_dsmem(r_ps_in[buf], l_ps_out[buf], 512, r_mbar[buf]);
        }

        if (own) {
            if (buf == 0) { mbar_wait(l_mbar[0], ph0); ph0 ^= 1; }
            else          { mbar_wait(l_mbar[1], ph1); ph1 ^= 1; }
            float s  = part + ps_in[buf][jloc] + xv + bias;
            float hn = tanh_approx(s);
            g_enc[((size_t)batch * Tn + t) * Hn + tid] = hn;
            h_cur[jloc] = hn;   // safe: all FMA reads of h_cur finished before bar above
        }
        __syncthreads();
    }

    // keep smem alive until peer's in-flight bulk reads/writes are done
    asm volatile("barrier.cluster.arrive.aligned;" ::: "memory");
    asm volatile("barrier.cluster.wait.aligned;" ::: "memory");
}

// ---------------- kernel 3: mean + bd heads ----------------
__global__ void k_meanbd(const float* __restrict__ W_mean, const float* __restrict__ b_mean,
                         const float* __restrict__ W_bd,   const float* __restrict__ b_bd,
                         float* __restrict__ out_mean) {
    const int local = threadIdx.x;            // 0..191
    const int o  = local % 24;
    const int r  = local / 24;
    const int bt = blockIdx.x * 8 + r;        // 0..8191

    const float4* e4 = reinterpret_cast<const float4*>(g_enc + (size_t)bt * Hn);
    const float4* w4;
    float bias;
    if (o < Dn) { w4 = reinterpret_cast<const float4*>(W_mean + o * Hn);        bias = __ldg(b_mean + o); }
    else        { w4 = reinterpret_cast<const float4*>(W_bd + (o - Dn) * Hn);   bias = __ldg(b_bd + (o - Dn)); }

    float acc = 0.f;
#pragma unroll 8
    for (int k = 0; k < 64; k++) {
        float4 ev = __ldg(e4 + k);
        float4 wv = __ldg(w4 + k);
        acc += ev.x * wv.x + ev.y * wv.y + ev.z * wv.z + ev.w * wv.w;
    }
    acc += bias;
    if (o < Dn) out_mean[(size_t)bt * Dn + o] = acc;
    else        g_bd[(size_t)bt * (2 * Dn) + (o - Dn)] = acc;
}

// ---------------- kernel 4: build tridiagonal prec (B, D, T, T) ----------------
__global__ void __launch_bounds__(512) k_prec(float* __restrict__ prec) {
    const int idx = blockIdx.x * 512 + threadIdx.x;   // 0 .. 8388607
    const int c4  = idx & 127;                        // column group (4 cols)
    const int i   = (idx >> 7) & 511;                 // row within (t,t) block
    const int bd_ = idx >> 16;                        // b*8 + d
    const int d   = bd_ & 7;
    const int b   = bd_ >> 3;

    float4 v = make_float4(0.f, 0.f, 0.f, 0.f);
    const int cb = c4 << 2;

    if (i >= cb - 1 && i <= cb + 4) {
        const size_t row = ((size_t)b * Tn + i) * 16;
        float diag_i = g_bd[row + d];
        float off_i  = g_bd[row + 8 + d];
        float diag_p = 0.f, off_p = 0.f;
        if (i > 0) {
            diag_p = g_bd[row - 16 + d];
            off_p  = g_bd[row - 16 + 8 + d];
        }
        float mainv  = diag_i * diag_i + off_p * off_p + EPSf;
        float supd_l = diag_p * off_p;   // column i-1
        float supd_r = diag_i * off_i;   // column i+1

        int c;
        c = cb + 0; v.x = (c == i) ? mainv : (c == i - 1) ? supd_l : (c == i + 1) ? supd_r : 0.f;
        c = cb + 1; v.y = (c == i) ? mainv : (c == i - 1) ? supd_l : (c == i + 1) ? supd_r : 0.f;
        c = cb + 2; v.z = (c == i) ? mainv : (c == i - 1) ? supd_l : (c == i + 1) ? supd_r : 0.f;
        c = cb + 3; v.w = (c == i) ? mainv : (c == i - 1) ? supd_l : (c == i + 1) ? supd_r : 0.f;
    }
    __stcs(reinterpret_cast<float4*>(prec) + idx, v);   // streaming: don't pollute L2
}

// ---------------- launch ----------------
extern "C" void kernel_launch(void* const* d_in, const int* in_sizes, int n_in,
                              void* d_out, int out_size) {
    const float* y      = (const float*)d_in[0];
    const float* W_ih   = (const float*)d_in[1];
    const float* W_hh   = (const float*)d_in[2];
    const float* b_ih   = (const float*)d_in[3];
    const float* b_hh   = (const float*)d_in[4];
    const float* W_mean = (const float*)d_in[5];
    const float* b_mean = (const float*)d_in[6];
    const float* W_bd   = (const float*)d_in[7];
    const float* b_bd   = (const float*)d_in[8];
    float* out = (float*)d_out;

    k_xproj<<<dim3(Tn / 4, Bn), 256>>>(y, W_ih, b_ih);
    k_scan<<<2 * Bn, 256>>>(W_hh, b_hh);
    k_meanbd<<<(Bn * Tn) / 8, 192>>>(W_mean, b_mean, W_bd, b_bd, out);
    k_prec<<<(Bn * Dn * Tn * Tn / 4) / 512, 512>>>(out + Bn * Tn * Dn);
}

// round 3
// speedup vs baseline: 1.3739x; 1.0456x over previous
#include <cuda_runtime.h>
#include <cstdint>

#define Bn   16
#define Tn   512
#define INn  128
#define Hn   256
#define Dn   8
#define EPSf 1e-5f

// ---------------- scratch (static device arrays; no allocation) ----------------
__device__ float g_xproj[Bn * Tn * Hn];   // 8 MB
__device__ float g_enc  [Bn * Tn * Hn];   // 8 MB
__device__ float g_bd   [Bn * Tn * 2 * Dn]; // 512 KB

// ---------------- helpers ----------------
__device__ __forceinline__ uint32_t smem_u32(const void* p) {
    uint32_t a;
    asm("{ .reg .u64 t; cvta.to.shared.u64 t, %1; cvt.u32.u64 %0, t; }"
        : "=r"(a) : "l"(p));
    return a;
}

__device__ __forceinline__ uint32_t cluster_rank() {
    uint32_t r;
    asm("mov.u32 %0, %%cluster_ctarank;" : "=r"(r));
    return r;
}

__device__ __forceinline__ uint32_t mapa_u32(uint32_t local_addr, uint32_t rank) {
    uint32_t r;
    asm("mapa.shared::cluster.u32 %0, %1, %2;" : "=r"(r) : "r"(local_addr), "r"(rank));
    return r;
}

__device__ __forceinline__ unsigned long long pack2(float x, float y) {
    unsigned long long r;
    asm("mov.b64 %0, {%1, %2};" : "=l"(r) : "f"(x), "f"(y));
    return r;
}
__device__ __forceinline__ void unpack2(unsigned long long v, float& x, float& y) {
    asm("mov.b64 {%0, %1}, %2;" : "=f"(x), "=f"(y) : "l"(v));
}
// packed fp32x2 FMA (Blackwell FFMA2): 2 fp32 MACs per instruction
__device__ __forceinline__ void ffma2(unsigned long long& d,
                                      unsigned long long a,
                                      unsigned long long b) {
    asm("fma.rn.f32x2 %0, %1, %2, %3;" : "=l"(d) : "l"(a), "l"(b), "l"(d));
}

__device__ __forceinline__ float tanh_approx(float x) {
    float r;
    asm("tanh.approx.f32 %0, %1;" : "=f"(r) : "f"(x));
    return r;
}

__device__ __forceinline__ void mbar_init(uint32_t addr, uint32_t count) {
    asm volatile("mbarrier.init.shared.b64 [%0], %1;" :: "r"(addr), "r"(count) : "memory");
}

__device__ __forceinline__ void mbar_arrive_expect_tx(uint32_t addr, uint32_t bytes) {
    asm volatile("mbarrier.arrive.expect_tx.shared.b64 _, [%0], %1;"
                 :: "r"(addr), "r"(bytes) : "memory");
}

__device__ __forceinline__ void mbar_wait(uint32_t addr, int phase) {
    asm volatile(
        "{\n\t"
        ".reg .pred P1;\n\t"
        "LAB_%=:\n\t"
        "mbarrier.try_wait.parity.acquire.cta.shared::cta.b64 P1, [%0], %1, 0x989680;\n\t"
        "@P1 bra DONE_%=;\n\t"
        "bra LAB_%=;\n\t"
        "DONE_%=:\n\t"
        "}"
        :: "r"(addr), "r"(phase) : "memory");
}

// async remote smem store with tx-completion on the remote mbarrier (no fence needed)
__device__ __forceinline__ void st_async_f32(uint32_t raddr, float v, uint32_t rmbar) {
    asm volatile(
        "st.async.shared::cluster.mbarrier::complete_tx::bytes.b32 [%0], %1, [%2];"
        :: "r"(raddr), "r"(__float_as_uint(v)), "r"(rmbar) : "memory");
}

// ---------------- kernel 1: x_proj = y @ W_ih^T + b_ih ----------------
__global__ void k_xproj(const float* __restrict__ y,
                        const float* __restrict__ W_ih,
                        const float* __restrict__ b_ih) {
    const int h  = threadIdx.x;       // 0..255
    const int b  = blockIdx.y;
    const int t0 = blockIdx.x * 4;

    const float4* Wr = reinterpret_cast<const float4*>(W_ih + h * INn);
    const float4* Y  = reinterpret_cast<const float4*>(y + ((size_t)b * Tn + t0) * INn);

    float a0 = 0.f, a1 = 0.f, a2 = 0.f, a3 = 0.f;
#pragma unroll 4
    for (int k = 0; k < 32; k++) {
        float4 wv = __ldg(Wr + k);
        float4 y0 = __ldg(Y + k);
        float4 y1 = __ldg(Y + 32 + k);
        float4 y2 = __ldg(Y + 64 + k);
        float4 y3 = __ldg(Y + 96 + k);
        a0 += wv.x * y0.x + wv.y * y0.y + wv.z * y0.z + wv.w * y0.w;
        a1 += wv.x * y1.x + wv.y * y1.y + wv.z * y1.z + wv.w * y1.w;
        a2 += wv.x * y2.x + wv.y * y2.y + wv.z * y2.z + wv.w * y2.w;
        a3 += wv.x * y3.x + wv.y * y3.y + wv.z * y3.z + wv.w * y3.w;
    }
    const float bias = __ldg(b_ih + h);
    size_t base = ((size_t)b * Tn + t0) * Hn + h;
    g_xproj[base]          = a0 + bias;
    g_xproj[base + Hn]     = a1 + bias;
    g_xproj[base + 2 * Hn] = a2 + bias;
    g_xproj[base + 3 * Hn] = a3 + bias;
}

// ---------------- kernel 2: RNN scan (st.async partial shipping) ----------------
// 32 CTAs, clusters of 2 (one per batch), 256 threads.
// CTA rank r owns h rows [r*128, r*128+128) and W columns [r*128, +128).
// Threads in warps 0-3 handle this CTA's OWN rows; warps 4-7 handle the peer's
// rows (high wid -> arbiter issues them first, so their st.asyncs leave early
// and the DSMEM flight overlaps the own-row FMA).
// Per step: every thread computes a 128-length dot (local k-half) for its row.
// Peer-row threads push their partial straight into the peer's ps_in slot via
// st.async (+tx on peer's mbar). Own-row threads wait for 512 incoming bytes,
// combine, tanh, write h. One __syncthreads per step.
__global__ void __cluster_dims__(2, 1, 1) __launch_bounds__(256, 1)
k_scan(const float* __restrict__ W_hh, const float* __restrict__ b_hh) {
    __shared__ __align__(16) float hbuf[2][128];   // local h half, double buffered
    __shared__ __align__(16) float ps_in[2][128];  // incoming peer partials
    __shared__ __align__(8) unsigned long long mbar[2];

    const int tid  = threadIdx.x;
    const int lidx = tid & 127;
    const unsigned rank = cluster_rank();
    const unsigned peer = rank ^ 1;
    const int batch = blockIdx.x >> 1;
    const bool own  = (tid < 128);                 // warps 0-3 = own rows
    // global output row: own threads -> rank half; warps 4-7 -> peer half
    const int jg = (int)((((unsigned)rank << 7) ^ (tid & 128)) | (unsigned)lidx);

    // register-resident weight slice: W_hh[jg, rank*128 .. +128)  (64 f32x2)
    unsigned long long w[64];
    {
        const float2* wr = reinterpret_cast<const float2*>(W_hh + (size_t)jg * Hn + (rank << 7));
#pragma unroll
        for (int i = 0; i < 64; i++) {
            float2 v = __ldg(wr + i);
            w[i] = pack2(v.x, v.y);
        }
    }
    const float bias = own ? __ldg(b_hh + jg) : 0.f;
    const float* xcol = g_xproj + (size_t)batch * Tn * Hn + jg;

    if (tid == 0) { mbar_init(smem_u32(&mbar[0]), 1); mbar_init(smem_u32(&mbar[1]), 1); }
    if (own) hbuf[0][lidx] = 0.f;   // h(-1) = 0
    __syncthreads();
    asm volatile("barrier.cluster.arrive.aligned;" ::: "memory");
    asm volatile("barrier.cluster.wait.aligned;" ::: "memory");

    // remote addresses (peer CTA): partial slot + mbar, per buffer
    const uint32_t r_ps[2]   = { mapa_u32(smem_u32(&ps_in[0][lidx]), peer),
                                 mapa_u32(smem_u32(&ps_in[1][lidx]), peer) };
    const uint32_t r_mbar[2] = { mapa_u32(smem_u32(&mbar[0]), peer),
                                 mapa_u32(smem_u32(&mbar[1]), peer) };
    const uint32_t l_mbar[2] = { smem_u32(&mbar[0]), smem_u32(&mbar[1]) };

    int ph[2] = {0, 0};
    float xv = own ? __ldg(xcol) : 0.f;   // x for t=0

    for (int t = 0; t < Tn; ++t) {
        const int buf = t & 1;
        const int nb  = buf ^ 1;

        // prefetch next x (own threads), latency hidden behind FMA
        float xnext = 0.f;
        if (own && (t + 1) < Tn) xnext = __ldg(xcol + (size_t)(t + 1) * Hn);

        // post tx expectation for this step's incoming 512 bytes
        if (tid == 0) mbar_arrive_expect_tx(l_mbar[buf], 512);

        // 128-length dot over local h half
        const float4* hp = reinterpret_cast<const float4*>(hbuf[buf]);
        unsigned long long acc0 = pack2(0.f, 0.f);
        unsigned long long acc1 = pack2(0.f, 0.f);
#pragma unroll
        for (int i = 0; i < 32; i++) {
            float4 hv = hp[i];
            ffma2(acc0, w[2 * i],     pack2(hv.x, hv.y));
            ffma2(acc1, w[2 * i + 1], pack2(hv.z, hv.w));
        }
        float a0, a1, c0, c1;
        unpack2(acc0, a0, a1);
        unpack2(acc1, c0, c1);
        const float part = (a0 + c0) + (a1 + c1);

        if (!own) {
            // push partial straight into peer's slot; tx counts on peer's mbar
            st_async_f32(r_ps[buf], part, r_mbar[buf]);
        } else {
            mbar_wait(l_mbar[buf], ph[buf]);
            ph[buf] ^= 1;
            float s  = part + ps_in[buf][lidx] + xv + bias;
            float hn = tanh_approx(s);
            xv = xnext;
            g_enc[((size_t)batch * Tn + t) * Hn + jg] = hn;
            hbuf[nb][lidx] = hn;
        }
        __syncthreads();
    }

    // keep smem/barriers alive until peer's in-flight st.asyncs complete
    asm volatile("barrier.cluster.arrive.aligned;" ::: "memory");
    asm volatile("barrier.cluster.wait.aligned;" ::: "memory");
}

// ---------------- kernel 3: mean + bd heads ----------------
__global__ void k_meanbd(const float* __restrict__ W_mean, const float* __restrict__ b_mean,
                         const float* __restrict__ W_bd,   const float* __restrict__ b_bd,
                         float* __restrict__ out_mean) {
    const int local = threadIdx.x;            // 0..191
    const int o  = local % 24;
    const int r  = local / 24;
    const int bt = blockIdx.x * 8 + r;        // 0..8191

    const float4* e4 = reinterpret_cast<const float4*>(g_enc + (size_t)bt * Hn);
    const float4* w4;
    float bias;
    if (o < Dn) { w4 = reinterpret_cast<const float4*>(W_mean + o * Hn);        bias = __ldg(b_mean + o); }
    else        { w4 = reinterpret_cast<const float4*>(W_bd + (o - Dn) * Hn);   bias = __ldg(b_bd + (o - Dn)); }

    float acc = 0.f;
#pragma unroll 8
    for (int k = 0; k < 64; k++) {
        float4 ev = __ldg(e4 + k);
        float4 wv = __ldg(w4 + k);
        acc += ev.x * wv.x + ev.y * wv.y + ev.z * wv.z + ev.w * wv.w;
    }
    acc += bias;
    if (o < Dn) out_mean[(size_t)bt * Dn + o] = acc;
    else        g_bd[(size_t)bt * (2 * Dn) + (o - Dn)] = acc;
}

// ---------------- kernel 4: build tridiagonal prec (B, D, T, T) ----------------
__global__ void __launch_bounds__(512) k_prec(float* __restrict__ prec) {
    const int idx = blockIdx.x * 512 + threadIdx.x;   // 0 .. 8388607
    const int c4  = idx & 127;                        // column group (4 cols)
    const int i   = (idx >> 7) & 511;                 // row within (t,t) block
    const int bd_ = idx >> 16;                        // b*8 + d
    const int d   = bd_ & 7;
    const int b   = bd_ >> 3;

    float4 v = make_float4(0.f, 0.f, 0.f, 0.f);
    const int cb = c4 << 2;

    if (i >= cb - 1 && i <= cb + 4) {
        const size_t row = ((size_t)b * Tn + i) * 16;
        float diag_i = g_bd[row + d];
        float off_i  = g_bd[row + 8 + d];
        float diag_p = 0.f, off_p = 0.f;
        if (i > 0) {
            diag_p = g_bd[row - 16 + d];
            off_p  = g_bd[row - 16 + 8 + d];
        }
        float mainv  = diag_i * diag_i + off_p * off_p + EPSf;
        float supd_l = diag_p * off_p;   // column i-1
        float supd_r = diag_i * off_i;   // column i+1

        int c;
        c = cb + 0; v.x = (c == i) ? mainv : (c == i - 1) ? supd_l : (c == i + 1) ? supd_r : 0.f;
        c = cb + 1; v.y = (c == i) ? mainv : (c == i - 1) ? supd_l : (c == i + 1) ? supd_r : 0.f;
        c = cb + 2; v.z = (c == i) ? mainv : (c == i - 1) ? supd_l : (c == i + 1) ? supd_r : 0.f;
        c = cb + 3; v.w = (c == i) ? mainv : (c == i - 1) ? supd_l : (c == i + 1) ? supd_r : 0.f;
    }
    __stcs(reinterpret_cast<float4*>(prec) + idx, v);   // streaming store
}

// ---------------- launch ----------------
extern "C" void kernel_launch(void* const* d_in, const int* in_sizes, int n_in,
                              void* d_out, int out_size) {
    const float* y      = (const float*)d_in[0];
    const float* W_ih   = (const float*)d_in[1];
    const float* W_hh   = (const float*)d_in[2];
    const float* b_ih   = (const float*)d_in[3];
    const float* b_hh   = (const float*)d_in[4];
    const float* W_mean = (const float*)d_in[5];
    const float* b_mean = (const float*)d_in[6];
    const float* W_bd   = (const float*)d_in[7];
    const float* b_bd   = (const float*)d_in[8];
    float* out = (float*)d_out;

    k_xproj<<<dim3(Tn / 4, Bn), 256>>>(y, W_ih, b_ih);
    k_scan<<<2 * Bn, 256>>>(W_hh, b_hh);
    k_meanbd<<<(Bn * Tn) / 8, 192>>>(W_mean, b_mean, W_bd, b_bd, out);
    k_prec<<<(Bn * Dn * Tn * Tn / 4) / 512, 512>>>(out + Bn * Tn * Dn);
}